// round 1
// baseline (speedup 1.0000x reference)
#include <cuda_runtime.h>
#include <cuda_bf16.h>
#include <cstdint>

// Problem constants
#define PB 4
#define PS 2048
#define PD 1024
#define PC 32
#define PNL 256      // N*L
#define PH 16
#define PDK 64
#define PCHUNK 64
#define PSCALE 0.125f   // 1/sqrt(64)
#define VALID_ROWS 1985 // S - (CHUNK-1)

// -------------------- scratch (static device memory, no allocs) --------------------
__device__ float g_X [PB*PS*PD];          // layernormed+padded input, (8192,1024)
__device__ float g_Q [PB*PS*PD];          // (8192,1024)
__device__ float g_K [PB*PC*PNL*PD];      // (32768,1024)
__device__ float g_V [PB*PC*PNL*PD];      // (32768,1024)
__device__ float g_AO[PB*PS*PD];          // attention output, (8192,1024)

// -------------------- helpers --------------------
__device__ __forceinline__ uint32_t f2tf32(float f){
    uint32_t r; asm("cvt.rna.tf32.f32 %0, %1;" : "=r"(r) : "f"(f)); return r;
}
__device__ __forceinline__ void mma_tf32(float c[4], const uint32_t a[4], const uint32_t b[2]){
    asm volatile("mma.sync.aligned.m16n8k8.row.col.f32.tf32.tf32.f32 "
        "{%0,%1,%2,%3},{%4,%5,%6,%7},{%8,%9},{%0,%1,%2,%3};\n"
        : "+f"(c[0]),"+f"(c[1]),"+f"(c[2]),"+f"(c[3])
        : "r"(a[0]),"r"(a[1]),"r"(a[2]),"r"(a[3]),"r"(b[0]),"r"(b[1]));
}
__device__ __forceinline__ void cp16(void* s, const void* g){
    uint32_t a = (uint32_t)__cvta_generic_to_shared(s);
    asm volatile("cp.async.cg.shared.global [%0], [%1], 16;" :: "r"(a), "l"(g));
}

// -------------------- LayerNorm (+pad) --------------------
// grid = 8192 (= B*2048 rows of X), 256 threads. X[row] = LN(h[b, r+63]) or 0 for r>=1985.
__global__ void __launch_bounds__(256) ln_kernel(
    const float* __restrict__ h, const float* __restrict__ gamma,
    const float* __restrict__ beta, float* __restrict__ X)
{
    const int row = blockIdx.x;
    const int b = row >> 11, r = row & 2047;
    const int tid = threadIdx.x;
    float* xo = X + (long)row * PD;
    if (r >= VALID_ROWS){
        *(float4*)&xo[tid*4] = make_float4(0.f,0.f,0.f,0.f);
        return;
    }
    const float* hp = h + ((long)b*PS + r + (PCHUNK-1)) * PD;
    float4 v = *(const float4*)&hp[tid*4];
    float s  = v.x + v.y + v.z + v.w;
    float sq = v.x*v.x + v.y*v.y + v.z*v.z + v.w*v.w;
#pragma unroll
    for (int o=16;o;o>>=1){
        s  += __shfl_down_sync(0xffffffffu, s,  o);
        sq += __shfl_down_sync(0xffffffffu, sq, o);
    }
    __shared__ float rs_[8], rq_[8];
    __shared__ float mu_s, rstd_s;
    const int wid = tid>>5, lane = tid&31;
    if (!lane){ rs_[wid]=s; rq_[wid]=sq; }
    __syncthreads();
    if (tid==0){
        float ts=0.f, tq=0.f;
#pragma unroll
        for (int i=0;i<8;i++){ ts+=rs_[i]; tq+=rq_[i]; }
        float mu = ts * (1.0f/PD);
        float var = tq * (1.0f/PD) - mu*mu;
        mu_s = mu; rstd_s = rsqrtf(var + 1e-5f);
    }
    __syncthreads();
    const float mu = mu_s, rstd = rstd_s;
    float4 g  = *(const float4*)&gamma[tid*4];
    float4 be = *(const float4*)&beta[tid*4];
    float4 o;
    o.x = (v.x-mu)*rstd*g.x + be.x;
    o.y = (v.y-mu)*rstd*g.y + be.y;
    o.z = (v.z-mu)*rstd*g.z + be.z;
    o.w = (v.w-mu)*rstd*g.w + be.w;
    *(float4*)&xo[tid*4] = o;
}

// -------------------- TF32 GEMM: C(M,1024) = A(M,1024) @ W(1024,1024) + bias --------------------
// Tile 128x128x32, 256 threads (8 warps, 4x2), warp tile 32x64, cp.async double buffered.
// EPI=0: plain store. EPI=1: shifted residual-add into d_out (out[b, r+63] = C[b,r] + h[b,r+63], r<1985).
#define GEMM_SMEM ((2*128*36 + 2*32*132) * 4)

template<int EPI>
__global__ void __launch_bounds__(256) gemm_tf32_kernel(
    const float* __restrict__ A, const float* __restrict__ W,
    const float* __restrict__ bias, float* __restrict__ Cout,
    const float* __restrict__ resid)
{
    extern __shared__ float sm[];
    float* As = sm;                 // [2][128][36]
    float* Bs = sm + 2*128*36;      // [2][32][132]
    const int tid = threadIdx.x;
    const int wid = tid >> 5, lane = tid & 31;
    const int wm = wid & 3, wn = wid >> 2;
    const int quad = lane >> 2, qt = lane & 3;
    const int bm = blockIdx.y, bn = blockIdx.x;
    const long arow0 = (long)bm * 128;

    float acc[2][8][4] = {};

    // prologue load of k-tile 0
    {
#pragma unroll
        for (int i=0;i<4;i++){
            int idx = tid + i*256;
            int r = idx >> 3, c4 = idx & 7;
            cp16(&As[(0*128 + r)*36 + c4*4], &A[(arow0 + r)*1024 + 0*32 + c4*4]);
        }
#pragma unroll
        for (int i=0;i<4;i++){
            int idx = tid + i*256;
            int r = idx >> 5, c4 = idx & 31;
            cp16(&Bs[(0*32 + r)*132 + c4*4], &W[(long)(0*32 + r)*1024 + bn*128 + c4*4]);
        }
        asm volatile("cp.async.commit_group;");
    }

    for (int kt = 0; kt < 32; ++kt){
        const int buf = kt & 1;
        if (kt + 1 < 32){
            const int nb = buf ^ 1;
#pragma unroll
            for (int i=0;i<4;i++){
                int idx = tid + i*256;
                int r = idx >> 3, c4 = idx & 7;
                cp16(&As[(nb*128 + r)*36 + c4*4], &A[(arow0 + r)*1024 + (kt+1)*32 + c4*4]);
            }
#pragma unroll
            for (int i=0;i<4;i++){
                int idx = tid + i*256;
                int r = idx >> 5, c4 = idx & 31;
                cp16(&Bs[(nb*32 + r)*132 + c4*4], &W[(long)((kt+1)*32 + r)*1024 + bn*128 + c4*4]);
            }
        }
        asm volatile("cp.async.commit_group;");
        asm volatile("cp.async.wait_group 1;");
        __syncthreads();

#pragma unroll
        for (int kk=0; kk<32; kk+=8){
            uint32_t af[2][4];
#pragma unroll
            for (int mi=0; mi<2; mi++){
                const int mb = wm*32 + mi*16;
                af[mi][0]=f2tf32(As[(buf*128 + mb+quad  )*36 + kk+qt  ]);
                af[mi][1]=f2tf32(As[(buf*128 + mb+quad+8)*36 + kk+qt  ]);
                af[mi][2]=f2tf32(As[(buf*128 + mb+quad  )*36 + kk+qt+4]);
                af[mi][3]=f2tf32(As[(buf*128 + mb+quad+8)*36 + kk+qt+4]);
            }
            uint32_t bf[8][2];
#pragma unroll
            for (int ni=0; ni<8; ni++){
                const int nb2 = wn*64 + ni*8;
                bf[ni][0]=f2tf32(Bs[(buf*32 + kk+qt  )*132 + nb2+quad]);
                bf[ni][1]=f2tf32(Bs[(buf*32 + kk+qt+4)*132 + nb2+quad]);
            }
#pragma unroll
            for (int mi=0;mi<2;mi++)
#pragma unroll
                for (int ni=0;ni<8;ni++)
                    mma_tf32(acc[mi][ni], af[mi], bf[ni]);
        }
        __syncthreads();
    }

    // epilogue
#pragma unroll
    for (int mi=0;mi<2;mi++){
#pragma unroll
        for (int ni=0;ni<8;ni++){
            const int gr0 = bm*128 + wm*32 + mi*16 + quad;
            const int gc  = bn*128 + wn*64 + ni*8 + qt*2;
            const float b0 = bias[gc], b1 = bias[gc+1];
#pragma unroll
            for (int half=0; half<2; half++){
                const int gr = gr0 + half*8;
                const float v0 = acc[mi][ni][half*2+0] + b0;
                const float v1 = acc[mi][ni][half*2+1] + b1;
                if (EPI == 0){
                    Cout[(long)gr*1024 + gc]     = v0;
                    Cout[(long)gr*1024 + gc + 1] = v1;
                } else {
                    const int b = gr >> 11, r = gr & 2047;
                    if (r < VALID_ROWS){
                        const long o = ((long)b*PS + r + (PCHUNK-1))*PD + gc;
                        Cout[o]   = v0 + resid[o];
                        Cout[o+1] = v1 + resid[o+1];
                    }
                }
            }
        }
    }
}

// -------------------- attention: per (b,c,h) block --------------------
// 64x64 q, 256x64 k/v. S = q k^T * scale (mma), fp32 softmax in smem, O = P v (mma).
#define ATT_SMEM ((64*72*2 + 64*260) * 4)

__global__ void __launch_bounds__(128) attn_kernel(
    const float* __restrict__ Q, const float* __restrict__ Kb,
    const float* __restrict__ Vb, float* __restrict__ AO)
{
    extern __shared__ float sm[];
    float* Qs  = sm;            // [64][72]
    float* KVs = sm + 64*72;    // [64][72]
    float* Ss  = sm + 2*64*72;  // [64][260]
    const int hh = blockIdx.x, c = blockIdx.y, b = blockIdx.z;
    const int tid = threadIdx.x, w = tid>>5, lane = tid&31;
    const int quad = lane>>2, qt = lane&3;
    const long qbase  = ((long)((b*PC + c)*PCHUNK))*PD + hh*PDK;
    const long kvbase = ((long)((b*PC + c)*PNL ))*PD + hh*PDK;

    // load Q (64 x 64)
#pragma unroll
    for (int it=0; it<8; it++){
        int idx = tid + it*128;
        int r = idx>>4, c4 = idx&15;
        *(float4*)&Qs[r*72 + c4*4] = *(const float4*)&Q[qbase + (long)r*1024 + c4*4];
    }

    // ---- S = q k^T, tiled over j ----
    for (int jt=0; jt<4; jt++){
        __syncthreads();
#pragma unroll
        for (int it=0; it<8; it++){
            int idx = tid + it*128;
            int r = idx>>4, c4 = idx&15;
            *(float4*)&KVs[r*72 + c4*4] =
                *(const float4*)&Kb[kvbase + (long)(jt*64 + r)*1024 + c4*4];
        }
        __syncthreads();
        float acc[8][4] = {};
#pragma unroll
        for (int kk=0; kk<64; kk+=8){
            uint32_t af[4];
            const int ib = w*16;
            af[0]=f2tf32(Qs[(ib+quad  )*72 + kk+qt  ]);
            af[1]=f2tf32(Qs[(ib+quad+8)*72 + kk+qt  ]);
            af[2]=f2tf32(Qs[(ib+quad  )*72 + kk+qt+4]);
            af[3]=f2tf32(Qs[(ib+quad+8)*72 + kk+qt+4]);
#pragma unroll
            for (int ni=0; ni<8; ni++){
                uint32_t bf[2];
                bf[0]=f2tf32(KVs[(ni*8+quad)*72 + kk+qt  ]);
                bf[1]=f2tf32(KVs[(ni*8+quad)*72 + kk+qt+4]);
                mma_tf32(acc[ni], af, bf);
            }
        }
#pragma unroll
        for (int ni=0; ni<8; ni++){
            const int i0 = w*16 + quad;
            const int j0 = jt*64 + ni*8 + qt*2;
            Ss[i0*260 + j0]       = acc[ni][0]*PSCALE;
            Ss[i0*260 + j0+1]     = acc[ni][1]*PSCALE;
            Ss[(i0+8)*260 + j0]   = acc[ni][2]*PSCALE;
            Ss[(i0+8)*260 + j0+1] = acc[ni][3]*PSCALE;
        }
    }
    __syncthreads();

    // ---- softmax over 256 cols, one thread per row ----
    if (tid < 64){
        float* row = &Ss[tid*260];
        float m = -1e30f;
        for (int j=0;j<256;j++) m = fmaxf(m, row[j]);
        float ssum = 0.f;
        for (int j=0;j<256;j++){ float ev = __expf(row[j]-m); row[j]=ev; ssum+=ev; }
        const float inv = 1.0f/ssum;
        for (int j=0;j<256;j++) row[j]*=inv;
    }

    // ---- O = P @ V ----
    float accO[8][4] = {};
    for (int jt=0; jt<4; jt++){
        __syncthreads();
#pragma unroll
        for (int it=0; it<8; it++){
            int idx = tid + it*128;
            int r = idx>>4, c4 = idx&15;
            *(float4*)&KVs[r*72 + c4*4] =
                *(const float4*)&Vb[kvbase + (long)(jt*64 + r)*1024 + c4*4];
        }
        __syncthreads();
#pragma unroll
        for (int kk=0; kk<64; kk+=8){
            uint32_t af[4];
            const int ib = w*16;
            const int jcol = jt*64 + kk;
            af[0]=f2tf32(Ss[(ib+quad  )*260 + jcol+qt  ]);
            af[1]=f2tf32(Ss[(ib+quad+8)*260 + jcol+qt  ]);
            af[2]=f2tf32(Ss[(ib+quad  )*260 + jcol+qt+4]);
            af[3]=f2tf32(Ss[(ib+quad+8)*260 + jcol+qt+4]);
#pragma unroll
            for (int ni=0; ni<8; ni++){
                uint32_t bf[2];
                bf[0]=f2tf32(KVs[(kk+qt  )*72 + ni*8+quad]);
                bf[1]=f2tf32(KVs[(kk+qt+4)*72 + ni*8+quad]);
                mma_tf32(accO[ni], af, bf);
            }
        }
    }
#pragma unroll
    for (int ni=0; ni<8; ni++){
        const int i0 = w*16 + quad;
        const int d0 = ni*8 + qt*2;
        AO[qbase + (long)i0*1024 + d0]       = accO[ni][0];
        AO[qbase + (long)i0*1024 + d0+1]     = accO[ni][1];
        AO[qbase + (long)(i0+8)*1024 + d0]   = accO[ni][2];
        AO[qbase + (long)(i0+8)*1024 + d0+1] = accO[ni][3];
    }
}

// -------------------- copy first 63 rows of residual per batch --------------------
__global__ void copy_head_kernel(const float* __restrict__ h, float* __restrict__ out){
    const int idx = blockIdx.x*256 + threadIdx.x;  // float4 index
    if (idx >= PB*(PCHUNK-1)*(PD/4)) return;
    const int b = idx / ((PCHUNK-1)*(PD/4));
    const int rem = idx % ((PCHUNK-1)*(PD/4));
    const int s = rem >> 8, c4 = rem & 255;
    const long o = ((long)b*PS + s)*PD + c4*4;
    *(float4*)&out[o] = *(const float4*)&h[o];
}

// -------------------- launch --------------------
extern "C" void kernel_launch(void* const* d_in, const int* in_sizes, int n_in,
                              void* d_out, int out_size)
{
    const float* h     = (const float*)d_in[0];
    const float* e     = (const float*)d_in[1];
    const float* Wq    = (const float*)d_in[2];
    const float* bq    = (const float*)d_in[3];
    const float* Wk    = (const float*)d_in[4];
    const float* bk    = (const float*)d_in[5];
    const float* Wv    = (const float*)d_in[6];
    const float* bv    = (const float*)d_in[7];
    const float* Wo    = (const float*)d_in[8];
    const float* bo    = (const float*)d_in[9];
    const float* gamma = (const float*)d_in[10];
    const float* beta  = (const float*)d_in[11];
    float* out = (float*)d_out;

    void *pX,*pQ,*pK,*pV,*pA;
    cudaGetSymbolAddress(&pX, g_X);
    cudaGetSymbolAddress(&pQ, g_Q);
    cudaGetSymbolAddress(&pK, g_K);
    cudaGetSymbolAddress(&pV, g_V);
    cudaGetSymbolAddress(&pA, g_AO);

    cudaFuncSetAttribute(gemm_tf32_kernel<0>, cudaFuncAttributeMaxDynamicSharedMemorySize, GEMM_SMEM);
    cudaFuncSetAttribute(gemm_tf32_kernel<1>, cudaFuncAttributeMaxDynamicSharedMemorySize, GEMM_SMEM);
    cudaFuncSetAttribute(attn_kernel,         cudaFuncAttributeMaxDynamicSharedMemorySize, ATT_SMEM);

    // 1) layernorm + pad into X
    ln_kernel<<<PB*PS/1, 256>>>(h, gamma, beta, (float*)pX);
    // 2) Q = X @ Wq + bq        (M=8192)
    gemm_tf32_kernel<0><<<dim3(8,64),  256, GEMM_SMEM>>>((const float*)pX, Wq, bq, (float*)pQ, nullptr);
    // 3) K = e @ Wk + bk        (M=32768)
    gemm_tf32_kernel<0><<<dim3(8,256), 256, GEMM_SMEM>>>(e, Wk, bk, (float*)pK, nullptr);
    // 4) V = e @ Wv + bv
    gemm_tf32_kernel<0><<<dim3(8,256), 256, GEMM_SMEM>>>(e, Wv, bv, (float*)pV, nullptr);
    // 5) attention per (h, c, b)
    attn_kernel<<<dim3(PH, PC, PB), 128, ATT_SMEM>>>((const float*)pQ, (const float*)pK,
                                                     (const float*)pV, (float*)pA);
    // 6) out = shift(AO @ Wo + bo) + h   (rows 63..2047)
    gemm_tf32_kernel<1><<<dim3(8,64),  256, GEMM_SMEM>>>((const float*)pA, Wo, bo, out, h);
    // 7) out rows 0..62 = h
    copy_head_kernel<<<(PB*(PCHUNK-1)*(PD/4) + 255)/256, 256>>>(h, out);
}

// round 3
// speedup vs baseline: 1.0072x; 1.0072x over previous
#include <cuda_runtime.h>
#include <cuda_bf16.h>
#include <cstdint>

// Problem constants
#define PB 4
#define PS 2048
#define PD 1024
#define PC 32
#define PNL 256
#define PH 16
#define PDK 64
#define PCHUNK 64
#define PSCALE 0.125f
#define VALID_ROWS 1985

// -------------------- scratch --------------------
__device__ float g_X [PB*PS*PD];          // LN output, tf32 bits, k-permuted
__device__ float g_E [PB*PC*PNL*PD];      // e converted to tf32 bits, k-permuted
__device__ float g_Q [PB*PS*PD];          // fp32
__device__ float g_K [PB*PC*PNL*PD];      // fp32
__device__ float g_V [PB*PC*PNL*PD];      // fp32
__device__ float g_AO[PB*PS*PD];          // attn out, tf32 bits, k-permuted
__device__ float g_Wt[4*PD*PD];           // W^T, tf32 bits, k-permuted: [N][K]

// -------------------- helpers --------------------
__device__ __forceinline__ uint32_t f2tf32(float f){
    uint32_t r; asm("cvt.rna.tf32.f32 %0, %1;" : "=r"(r) : "f"(f)); return r;
}
__device__ __forceinline__ float f2tf32f(float f){
    return __uint_as_float(f2tf32(f));
}
__device__ __forceinline__ void mma_tf32(float c[4], uint32_t a0, uint32_t a1, uint32_t a2,
                                         uint32_t a3, uint32_t b0, uint32_t b1){
    asm volatile("mma.sync.aligned.m16n8k8.row.col.f32.tf32.tf32.f32 "
        "{%0,%1,%2,%3},{%4,%5,%6,%7},{%8,%9},{%0,%1,%2,%3};\n"
        : "+f"(c[0]),"+f"(c[1]),"+f"(c[2]),"+f"(c[3])
        : "r"(a0),"r"(a1),"r"(a2),"r"(a3),"r"(b0),"r"(b1));
}
__device__ __forceinline__ void cp16(uint32_t s, const void* g){
    asm volatile("cp.async.cg.shared.global [%0], [%1], 16;" :: "r"(s), "l"(g));
}
__device__ __forceinline__ uint32_t smem_u32(const void* p){
    uint32_t a;
    asm("{ .reg .u64 t; cvta.to.shared.u64 t, %1; cvt.u32.u64 %0, t; }" : "=r"(a) : "l"(p));
    return a;
}

// k-permutation within each 32-float block:
//   forward: j -> pos = (j>>3)*8 + (j&3)*2 + ((j>>2)&1)
//   inverse: p -> j   = (p>>3)*8 + (p&1)*4 + ((p&7)>>1)
__device__ __forceinline__ int permpos(int j){ return (j & ~7) | ((j&3)<<1) | ((j>>2)&1); }
__device__ __forceinline__ int invperm(int p){ return (p & ~7) | ((p&1)<<2) | ((p&7)>>1); }

// -------------------- TF32 GEMM --------------------
// C(M,1024) = A(M,1024) @ Wt^T + bias.  A, Wt are tf32-bit, k-permuted.
// Tile 128x128x32, 3-stage cp.async, 8 warps (4m x 2n), warp tile 32x64.
// smem: 3 stages x (A 128x32 + B 128x32) floats = 96KB.
#define NS 32
#define G_SMEM (3*8192*4)

template<int EPI>
__global__ void __launch_bounds__(256, 2) gemm_tf32_kernel(
    const float* __restrict__ A, const float* __restrict__ Bt,
    const float* __restrict__ bias, float* __restrict__ Cout,
    const float* __restrict__ resid)
{
    extern __shared__ float sm[];
    const uint32_t smem_base = smem_u32(sm);
    const int tid = threadIdx.x;
    const int wid = tid >> 5, lane = tid & 31;
    const int wm = wid & 3, wn = wid >> 2;
    const int quad = lane >> 2, qt = lane & 3;
    const int bm = blockIdx.y, bn = blockIdx.x;
    const long arow0 = (long)bm * 128;
    const long brow0 = (long)bn * 128;

    const int t1 = qt >> 1;           // chunk sub-index
    const int t2 = (qt & 1) * 2;      // word within chunk

    float acc[2][8][4] = {};

    // stage loader: 4 A-chunks + 4 B-chunks per thread
    auto load_stage = [&](int kt, int s){
        const int sb = s * 8192;
#pragma unroll
        for (int i = 0; i < 4; i++){
            const int idx = i*256 + tid;
            const int r = idx >> 3, cc = idx & 7;
            const int sc = cc ^ (r & 7);
            cp16(smem_base + (sb + r*32 + sc*4)*4,
                 &A[(arow0 + r)*1024 + kt*32 + cc*4]);
            cp16(smem_base + (sb + 4096 + r*32 + sc*4)*4,
                 &Bt[(brow0 + r)*1024 + kt*32 + cc*4]);
        }
    };

    load_stage(0, 0); asm volatile("cp.async.commit_group;" ::: "memory");
    load_stage(1, 1); asm volatile("cp.async.commit_group;" ::: "memory");

    for (int kt = 0; kt < NS; ++kt){
        if (kt < NS-1) asm volatile("cp.async.wait_group 1;" ::: "memory");
        else           asm volatile("cp.async.wait_group 0;" ::: "memory");
        __syncthreads();
        if (kt + 2 < NS){
            int s2 = (kt + 2) % 3;
            load_stage(kt + 2, s2);
            asm volatile("cp.async.commit_group;" ::: "memory");
        }
        const int sb = (kt % 3) * 8192;
        const float* Asm = sm + sb;
        const float* Bsm = sm + sb + 4096;

#pragma unroll
        for (int g = 0; g < 4; ++g){
            // A fragments: 2 m-tiles x 2 row-halves, LDS.64 each
            float2 a[2][2];
#pragma unroll
            for (int mi = 0; mi < 2; ++mi){
                const int r0 = wm*32 + mi*16 + quad;
#pragma unroll
                for (int hr = 0; hr < 2; ++hr){
                    const int r = r0 + hr*8;
                    const int w = r*32 + (((2*g + t1) ^ (r & 7)) << 2) + t2;
                    a[mi][hr] = *(const float2*)&Asm[w];
                }
            }
            // B fragments: 8 n-tiles
            float2 bv[8];
#pragma unroll
            for (int ni = 0; ni < 8; ++ni){
                const int n = wn*64 + ni*8 + quad;
                const int w = n*32 + (((2*g + t1) ^ (n & 7)) << 2) + t2;
                bv[ni] = *(const float2*)&Bsm[w];
            }
#pragma unroll
            for (int mi = 0; mi < 2; ++mi)
#pragma unroll
                for (int ni = 0; ni < 8; ++ni)
                    mma_tf32(acc[mi][ni],
                             __float_as_uint(a[mi][0].x), __float_as_uint(a[mi][1].x),
                             __float_as_uint(a[mi][0].y), __float_as_uint(a[mi][1].y),
                             __float_as_uint(bv[ni].x),   __float_as_uint(bv[ni].y));
        }
        __syncthreads();
    }

    // epilogue
#pragma unroll
    for (int mi = 0; mi < 2; ++mi){
#pragma unroll
        for (int ni = 0; ni < 8; ++ni){
            const int gr0 = bm*128 + wm*32 + mi*16 + quad;
            const int gc  = bn*128 + wn*64 + ni*8 + qt*2;
            const float b0 = bias[gc], b1 = bias[gc+1];
#pragma unroll
            for (int half = 0; half < 2; ++half){
                const int gr = gr0 + half*8;
                const float v0 = acc[mi][ni][half*2+0] + b0;
                const float v1 = acc[mi][ni][half*2+1] + b1;
                if (EPI == 0){
                    Cout[(long)gr*1024 + gc]     = v0;
                    Cout[(long)gr*1024 + gc + 1] = v1;
                } else {
                    const int b = gr >> 11, r = gr & 2047;
                    if (r < VALID_ROWS){
                        const long o = ((long)b*PS + r + (PCHUNK-1))*PD + gc;
                        Cout[o]   = v0 + resid[o];
                        Cout[o+1] = v1 + resid[o+1];
                    }
                }
            }
        }
    }
}

// -------------------- e -> tf32 + k-permute --------------------
__global__ void __launch_bounds__(256) convert_e_kernel(const float* __restrict__ e,
                                                        float* __restrict__ E){
    const long ci = (long)blockIdx.x*256 + threadIdx.x;   // float4 chunk id
    const long f0 = ci * 4;
    const long base = f0 & ~31L;
    const int p0 = (int)(f0 & 31);
    float4 v;
    v.x = f2tf32f(e[base + invperm(p0+0)]);
    v.y = f2tf32f(e[base + invperm(p0+1)]);
    v.z = f2tf32f(e[base + invperm(p0+2)]);
    v.w = f2tf32f(e[base + invperm(p0+3)]);
    *(float4*)&E[f0] = v;
}

// -------------------- weight transpose + tf32 + k-permute --------------------
// dst[n][perm(k)] = tf32(src[k][n])
__global__ void __launch_bounds__(256) transpose_kernel(const float* __restrict__ src,
                                                        float* __restrict__ dst){
    __shared__ float t[32][33];
    const int tx = threadIdx.x, ty = threadIdx.y;
    int x = blockIdx.x*32 + tx;
    int y = blockIdx.y*32 + ty;
#pragma unroll
    for (int j=0;j<32;j+=8) t[ty+j][tx] = src[(long)(y+j)*1024 + x];
    __syncthreads();
    const int xp = blockIdx.y*32 + permpos(tx);   // permuted k position
    y = blockIdx.x*32 + ty;
#pragma unroll
    for (int j=0;j<32;j+=8) dst[(long)(y+j)*1024 + xp] = f2tf32f(t[tx][ty+j]);
}

// -------------------- LayerNorm (+pad), tf32+permuted output --------------------
__global__ void __launch_bounds__(256) ln_kernel(
    const float* __restrict__ h, const float* __restrict__ gamma,
    const float* __restrict__ beta, float* __restrict__ X)
{
    const int row = blockIdx.x;
    const int b = row >> 11, r = row & 2047;
    const int tid = threadIdx.x;
    float* xo = X + (long)row * PD;
    if (r >= VALID_ROWS){
        *(float4*)&xo[tid*4] = make_float4(0.f,0.f,0.f,0.f);
        return;
    }
    const float* hp = h + ((long)b*PS + r + (PCHUNK-1)) * PD;
    float4 v = *(const float4*)&hp[tid*4];
    float s  = v.x + v.y + v.z + v.w;
    float sq = v.x*v.x + v.y*v.y + v.z*v.z + v.w*v.w;
#pragma unroll
    for (int o=16;o;o>>=1){
        s  += __shfl_down_sync(0xffffffffu, s,  o);
        sq += __shfl_down_sync(0xffffffffu, sq, o);
    }
    __shared__ float rs_[8], rq_[8];
    __shared__ float mu_s, rstd_s;
    __shared__ float rowbuf[1024];
    const int wid = tid>>5, lane = tid&31;
    if (!lane){ rs_[wid]=s; rq_[wid]=sq; }
    __syncthreads();
    if (tid==0){
        float ts=0.f, tq=0.f;
#pragma unroll
        for (int i=0;i<8;i++){ ts+=rs_[i]; tq+=rq_[i]; }
        float mu = ts * (1.0f/PD);
        float var = tq * (1.0f/PD) - mu*mu;
        mu_s = mu; rstd_s = rsqrtf(var + 1e-5f);
    }
    __syncthreads();
    const float mu = mu_s, rstd = rstd_s;
    float4 g  = *(const float4*)&gamma[tid*4];
    float4 be = *(const float4*)&beta[tid*4];
    rowbuf[tid*4+0] = (v.x-mu)*rstd*g.x + be.x;
    rowbuf[tid*4+1] = (v.y-mu)*rstd*g.y + be.y;
    rowbuf[tid*4+2] = (v.z-mu)*rstd*g.z + be.z;
    rowbuf[tid*4+3] = (v.w-mu)*rstd*g.w + be.w;
    __syncthreads();
    const int f0 = tid*4;
    const int base = f0 & ~31;
    const int p0 = f0 & 31;
    float4 o;
    o.x = f2tf32f(rowbuf[base + invperm(p0+0)]);
    o.y = f2tf32f(rowbuf[base + invperm(p0+1)]);
    o.z = f2tf32f(rowbuf[base + invperm(p0+2)]);
    o.w = f2tf32f(rowbuf[base + invperm(p0+3)]);
    *(float4*)&xo[f0] = o;
}

// -------------------- attention (per b,c,h), legacy mma --------------------
#define ATT_SMEM ((64*72*2 + 64*260) * 4)

__global__ void __launch_bounds__(128) attn_kernel(
    const float* __restrict__ Q, const float* __restrict__ Kb,
    const float* __restrict__ Vb, float* __restrict__ AO)
{
    extern __shared__ float sm[];
    float* Qs  = sm;
    float* KVs = sm + 64*72;
    float* Ss  = sm + 2*64*72;
    const int hh = blockIdx.x, c = blockIdx.y, b = blockIdx.z;
    const int tid = threadIdx.x, w = tid>>5, lane = tid&31;
    const int quad = lane>>2, qt = lane&3;
    const long qbase  = ((long)((b*PC + c)*PCHUNK))*PD + hh*PDK;
    const long kvbase = ((long)((b*PC + c)*PNL ))*PD + hh*PDK;

#pragma unroll
    for (int it=0; it<8; it++){
        int idx = tid + it*128;
        int r = idx>>4, c4 = idx&15;
        *(float4*)&Qs[r*72 + c4*4] = *(const float4*)&Q[qbase + (long)r*1024 + c4*4];
    }

    for (int jt=0; jt<4; jt++){
        __syncthreads();
#pragma unroll
        for (int it=0; it<8; it++){
            int idx = tid + it*128;
            int r = idx>>4, c4 = idx&15;
            *(float4*)&KVs[r*72 + c4*4] =
                *(const float4*)&Kb[kvbase + (long)(jt*64 + r)*1024 + c4*4];
        }
        __syncthreads();
        float acc[8][4] = {};
#pragma unroll
        for (int kk=0; kk<64; kk+=8){
            uint32_t af[4];
            const int ib = w*16;
            af[0]=f2tf32(Qs[(ib+quad  )*72 + kk+qt  ]);
            af[1]=f2tf32(Qs[(ib+quad+8)*72 + kk+qt  ]);
            af[2]=f2tf32(Qs[(ib+quad  )*72 + kk+qt+4]);
            af[3]=f2tf32(Qs[(ib+quad+8)*72 + kk+qt+4]);
#pragma unroll
            for (int ni=0; ni<8; ni++){
                uint32_t b0=f2tf32(KVs[(ni*8+quad)*72 + kk+qt  ]);
                uint32_t b1=f2tf32(KVs[(ni*8+quad)*72 + kk+qt+4]);
                mma_tf32(acc[ni], af[0],af[1],af[2],af[3], b0,b1);
            }
        }
#pragma unroll
        for (int ni=0; ni<8; ni++){
            const int i0 = w*16 + quad;
            const int j0 = jt*64 + ni*8 + qt*2;
            Ss[i0*260 + j0]       = acc[ni][0]*PSCALE;
            Ss[i0*260 + j0+1]     = acc[ni][1]*PSCALE;
            Ss[(i0+8)*260 + j0]   = acc[ni][2]*PSCALE;
            Ss[(i0+8)*260 + j0+1] = acc[ni][3]*PSCALE;
        }
    }
    __syncthreads();

    if (tid < 64){
        float* row = &Ss[tid*260];
        float m = -1e30f;
        for (int j=0;j<256;j++) m = fmaxf(m, row[j]);
        float ssum = 0.f;
        for (int j=0;j<256;j++){ float ev = __expf(row[j]-m); row[j]=ev; ssum+=ev; }
        const float inv = 1.0f/ssum;
        for (int j=0;j<256;j++) row[j]*=inv;
    }

    float accO[8][4] = {};
    for (int jt=0; jt<4; jt++){
        __syncthreads();
#pragma unroll
        for (int it=0; it<8; it++){
            int idx = tid + it*128;
            int r = idx>>4, c4 = idx&15;
            *(float4*)&KVs[r*72 + c4*4] =
                *(const float4*)&Vb[kvbase + (long)(jt*64 + r)*1024 + c4*4];
        }
        __syncthreads();
#pragma unroll
        for (int kk=0; kk<64; kk+=8){
            uint32_t af[4];
            const int ib = w*16;
            const int jcol = jt*64 + kk;
            af[0]=f2tf32(Ss[(ib+quad  )*260 + jcol+qt  ]);
            af[1]=f2tf32(Ss[(ib+quad+8)*260 + jcol+qt  ]);
            af[2]=f2tf32(Ss[(ib+quad  )*260 + jcol+qt+4]);
            af[3]=f2tf32(Ss[(ib+quad+8)*260 + jcol+qt+4]);
#pragma unroll
            for (int ni=0; ni<8; ni++){
                uint32_t b0=f2tf32(KVs[(kk+qt  )*72 + ni*8+quad]);
                uint32_t b1=f2tf32(KVs[(kk+qt+4)*72 + ni*8+quad]);
                mma_tf32(accO[ni], af[0],af[1],af[2],af[3], b0,b1);
            }
        }
    }
    // store tf32-converted + k-permuted (feeds O-GEMM)
#pragma unroll
    for (int ni=0; ni<8; ni++){
        const int i0 = w*16 + quad;
        const int d0 = ni*8 + qt*2;
        const int cb = d0 & ~31;
        const int p0 = permpos(d0 & 31), p1 = permpos((d0+1) & 31);
        AO[qbase + (long)i0*1024 + cb + p0]       = f2tf32f(accO[ni][0]);
        AO[qbase + (long)i0*1024 + cb + p1]       = f2tf32f(accO[ni][1]);
        AO[qbase + (long)(i0+8)*1024 + cb + p0]   = f2tf32f(accO[ni][2]);
        AO[qbase + (long)(i0+8)*1024 + cb + p1]   = f2tf32f(accO[ni][3]);
    }
}

// -------------------- copy first 63 rows --------------------
__global__ void copy_head_kernel(const float* __restrict__ h, float* __restrict__ out){
    const int idx = blockIdx.x*256 + threadIdx.x;
    if (idx >= PB*(PCHUNK-1)*(PD/4)) return;
    const int b = idx / ((PCHUNK-1)*(PD/4));
    const int rem = idx % ((PCHUNK-1)*(PD/4));
    const int s = rem >> 8, c4 = rem & 255;
    const long o = ((long)b*PS + s)*PD + c4*4;
    *(float4*)&out[o] = *(const float4*)&h[o];
}

// -------------------- launch --------------------
extern "C" void kernel_launch(void* const* d_in, const int* in_sizes, int n_in,
                              void* d_out, int out_size)
{
    const float* h     = (const float*)d_in[0];
    const float* e     = (const float*)d_in[1];
    const float* Wq    = (const float*)d_in[2];
    const float* bq    = (const float*)d_in[3];
    const float* Wk    = (const float*)d_in[4];
    const float* bk    = (const float*)d_in[5];
    const float* Wv    = (const float*)d_in[6];
    const float* bv    = (const float*)d_in[7];
    const float* Wo    = (const float*)d_in[8];
    const float* bo    = (const float*)d_in[9];
    const float* gamma = (const float*)d_in[10];
    const float* beta  = (const float*)d_in[11];
    float* out = (float*)d_out;

    void *pX,*pE,*pQ,*pK,*pV,*pA,*pW;
    cudaGetSymbolAddress(&pX, g_X);
    cudaGetSymbolAddress(&pE, g_E);
    cudaGetSymbolAddress(&pQ, g_Q);
    cudaGetSymbolAddress(&pK, g_K);
    cudaGetSymbolAddress(&pV, g_V);
    cudaGetSymbolAddress(&pA, g_AO);
    cudaGetSymbolAddress(&pW, g_Wt);
    float* Wt = (float*)pW;

    cudaFuncSetAttribute(gemm_tf32_kernel<0>, cudaFuncAttributeMaxDynamicSharedMemorySize, G_SMEM);
    cudaFuncSetAttribute(gemm_tf32_kernel<1>, cudaFuncAttributeMaxDynamicSharedMemorySize, G_SMEM);
    cudaFuncSetAttribute(attn_kernel,         cudaFuncAttributeMaxDynamicSharedMemorySize, ATT_SMEM);

    // 0) operand preparation
    transpose_kernel<<<dim3(32,32), dim3(32,8)>>>(Wq, Wt + 0*PD*PD);
    transpose_kernel<<<dim3(32,32), dim3(32,8)>>>(Wk, Wt + 1*PD*PD);
    transpose_kernel<<<dim3(32,32), dim3(32,8)>>>(Wv, Wt + 2*PD*PD);
    transpose_kernel<<<dim3(32,32), dim3(32,8)>>>(Wo, Wt + 3*PD*PD);
    convert_e_kernel<<<PB*PC*PNL*PD/1024, 256>>>(e, (float*)pE);
    ln_kernel<<<PB*PS, 256>>>(h, gamma, beta, (float*)pX);
    // 1) projections
    gemm_tf32_kernel<0><<<dim3(8,64),  256, G_SMEM>>>((const float*)pX, Wt + 0*PD*PD, bq, (float*)pQ, nullptr);
    gemm_tf32_kernel<0><<<dim3(8,256), 256, G_SMEM>>>((const float*)pE, Wt + 1*PD*PD, bk, (float*)pK, nullptr);
    gemm_tf32_kernel<0><<<dim3(8,256), 256, G_SMEM>>>((const float*)pE, Wt + 2*PD*PD, bv, (float*)pV, nullptr);
    // 2) attention
    attn_kernel<<<dim3(PH, PC, PB), 128, ATT_SMEM>>>((const float*)pQ, (const float*)pK,
                                                     (const float*)pV, (float*)pA);
    // 3) output projection + shifted residual
    gemm_tf32_kernel<1><<<dim3(8,64),  256, G_SMEM>>>((const float*)pA, Wt + 3*PD*PD, bo, out, h);
    // 4) head rows
    copy_head_kernel<<<(PB*(PCHUNK-1)*(PD/4) + 255)/256, 256>>>(h, out);
}

// round 4
// speedup vs baseline: 1.8955x; 1.8820x over previous
#include <cuda_runtime.h>
#include <cuda_bf16.h>
#include <cstdint>

// Problem constants
#define PB 4
#define PS 2048
#define PD 1024
#define PC 32
#define PNL 256
#define PH 16
#define PDK 64
#define PCHUNK 64
#define PSCALE 0.125f
#define VALID_ROWS 1985

// -------------------- scratch --------------------
__device__ __nv_bfloat16 g_X [PB*PS*PD];        // LN output (bf16)
__device__ __nv_bfloat16 g_E [PB*PC*PNL*PD];    // e (bf16)
__device__ __nv_bfloat16 g_AO[PB*PS*PD];        // attn out (bf16)
__device__ __nv_bfloat16 g_Wt[4*PD*PD];         // W^T (bf16) [N][K]
__device__ float g_Q [PB*PS*PD];
__device__ float g_K [PB*PC*PNL*PD];
__device__ float g_V [PB*PC*PNL*PD];

// -------------------- helpers --------------------
__device__ __forceinline__ uint32_t f2tf32(float f){
    uint32_t r; asm("cvt.rna.tf32.f32 %0, %1;" : "=r"(r) : "f"(f)); return r;
}
__device__ __forceinline__ void mma_tf32(float c[4], uint32_t a0, uint32_t a1, uint32_t a2,
                                         uint32_t a3, uint32_t b0, uint32_t b1){
    asm volatile("mma.sync.aligned.m16n8k8.row.col.f32.tf32.tf32.f32 "
        "{%0,%1,%2,%3},{%4,%5,%6,%7},{%8,%9},{%0,%1,%2,%3};\n"
        : "+f"(c[0]),"+f"(c[1]),"+f"(c[2]),"+f"(c[3])
        : "r"(a0),"r"(a1),"r"(a2),"r"(a3),"r"(b0),"r"(b1));
}
__device__ __forceinline__ void mma_bf16(float c[4], uint32_t a0, uint32_t a1, uint32_t a2,
                                         uint32_t a3, uint32_t b0, uint32_t b1){
    asm volatile("mma.sync.aligned.m16n8k16.row.col.f32.bf16.bf16.f32 "
        "{%0,%1,%2,%3},{%4,%5,%6,%7},{%8,%9},{%0,%1,%2,%3};\n"
        : "+f"(c[0]),"+f"(c[1]),"+f"(c[2]),"+f"(c[3])
        : "r"(a0),"r"(a1),"r"(a2),"r"(a3),"r"(b0),"r"(b1));
}
__device__ __forceinline__ void cp16(uint32_t s, const void* g){
    asm volatile("cp.async.cg.shared.global [%0], [%1], 16;" :: "r"(s), "l"(g));
}
__device__ __forceinline__ uint32_t smem_u32(const void* p){
    uint32_t a;
    asm("{ .reg .u64 t; cvta.to.shared.u64 t, %1; cvt.u32.u64 %0, t; }" : "=r"(a) : "l"(p));
    return a;
}
__device__ __forceinline__ uint32_t lds32(const char* smbase, uint32_t off){
    return *(const uint32_t*)(smbase + off);
}

// -------------------- bf16 GEMM --------------------
// C(M,1024) = A(M,1024) @ Wt^T + bias. A, Wt bf16 row-major [row][K].
// CTA tile 128x128, k-tile 64 (128B rows), 3-stage cp.async, 8 warps (4m x 2n).
// smem/stage: A 16KB + B 16KB; 3 stages = 96KB; 2 CTAs/SM.
#define NS 16
#define G_SMEM (3*32768)

template<int EPI>
__global__ void __launch_bounds__(256, 2) gemm_bf16_kernel(
    const __nv_bfloat16* __restrict__ A, const __nv_bfloat16* __restrict__ Bt,
    const float* __restrict__ bias, float* __restrict__ Cout,
    const float* __restrict__ resid)
{
    extern __shared__ char smc[];
    const uint32_t smem_base = smem_u32(smc);
    const int tid = threadIdx.x;
    const int wid = tid >> 5, lane = tid & 31;
    const int wm = wid & 3, wn = wid >> 2;
    const int quad = lane >> 2, qt = lane & 3;
    const int bm = blockIdx.y, bn = blockIdx.x;
    const long arow0 = (long)bm * 128;
    const long brow0 = (long)bn * 128;

    float acc[2][8][4] = {};

    auto load_stage = [&](int kt, int s){
        const uint32_t sb = smem_base + s*32768;
#pragma unroll
        for (int i = 0; i < 4; i++){
            const int idx = i*256 + tid;
            const int r = idx >> 3, c = idx & 7;
            const int sc = c ^ (r & 7);
            cp16(sb + r*128 + sc*16,          &A [(arow0 + r)*1024 + kt*64 + c*8]);
            cp16(sb + 16384 + r*128 + sc*16,  &Bt[(brow0 + r)*1024 + kt*64 + c*8]);
        }
    };

    load_stage(0, 0); asm volatile("cp.async.commit_group;" ::: "memory");
    load_stage(1, 1); asm volatile("cp.async.commit_group;" ::: "memory");

    for (int kt = 0; kt < NS; ++kt){
        if (kt < NS-1) asm volatile("cp.async.wait_group 1;" ::: "memory");
        else           asm volatile("cp.async.wait_group 0;" ::: "memory");
        __syncthreads();
        if (kt + 2 < NS){
            load_stage(kt + 2, (kt + 2) % 3);
            asm volatile("cp.async.commit_group;" ::: "memory");
        }
        const char* Asm = smc + (kt % 3)*32768;
        const char* Bsm = Asm + 16384;

#pragma unroll
        for (int g = 0; g < 4; ++g){
            uint32_t a[2][4];
#pragma unroll
            for (int mi = 0; mi < 2; ++mi){
                const int r0 = wm*32 + mi*16 + quad;
                const int r1 = r0 + 8;
                a[mi][0] = lds32(Asm, r0*128 + ((2*g  ) ^ (r0 & 7))*16 + qt*4);
                a[mi][1] = lds32(Asm, r1*128 + ((2*g  ) ^ (r1 & 7))*16 + qt*4);
                a[mi][2] = lds32(Asm, r0*128 + ((2*g+1) ^ (r0 & 7))*16 + qt*4);
                a[mi][3] = lds32(Asm, r1*128 + ((2*g+1) ^ (r1 & 7))*16 + qt*4);
            }
            uint32_t bfr[8][2];
#pragma unroll
            for (int ni = 0; ni < 8; ++ni){
                const int n = wn*64 + ni*8 + quad;
                bfr[ni][0] = lds32(Bsm, n*128 + ((2*g  ) ^ (n & 7))*16 + qt*4);
                bfr[ni][1] = lds32(Bsm, n*128 + ((2*g+1) ^ (n & 7))*16 + qt*4);
            }
#pragma unroll
            for (int mi = 0; mi < 2; ++mi)
#pragma unroll
                for (int ni = 0; ni < 8; ++ni)
                    mma_bf16(acc[mi][ni], a[mi][0], a[mi][1], a[mi][2], a[mi][3],
                             bfr[ni][0], bfr[ni][1]);
        }
        __syncthreads();
    }

    // epilogue
#pragma unroll
    for (int mi = 0; mi < 2; ++mi){
#pragma unroll
        for (int ni = 0; ni < 8; ++ni){
            const int gr0 = bm*128 + wm*32 + mi*16 + quad;
            const int gc  = bn*128 + wn*64 + ni*8 + qt*2;
            const float b0 = bias[gc], b1 = bias[gc+1];
#pragma unroll
            for (int half = 0; half < 2; ++half){
                const int gr = gr0 + half*8;
                const float v0 = acc[mi][ni][half*2+0] + b0;
                const float v1 = acc[mi][ni][half*2+1] + b1;
                if (EPI == 0){
                    Cout[(long)gr*1024 + gc]     = v0;
                    Cout[(long)gr*1024 + gc + 1] = v1;
                } else {
                    const int b = gr >> 11, r = gr & 2047;
                    if (r < VALID_ROWS){
                        const long o = ((long)b*PS + r + (PCHUNK-1))*PD + gc;
                        Cout[o]   = v0 + resid[o];
                        Cout[o+1] = v1 + resid[o+1];
                    }
                }
            }
        }
    }
}

// -------------------- e -> bf16 --------------------
__global__ void __launch_bounds__(256) convert_e_kernel(const float* __restrict__ e,
                                                        __nv_bfloat16* __restrict__ E){
    const long i4 = ((long)blockIdx.x*256 + threadIdx.x) * 4;
    float4 v = *(const float4*)&e[i4];
    __nv_bfloat162 lo = __float22bfloat162_rn(make_float2(v.x, v.y));
    __nv_bfloat162 hi = __float22bfloat162_rn(make_float2(v.z, v.w));
    *(__nv_bfloat162*)&E[i4]     = lo;
    *(__nv_bfloat162*)&E[i4 + 2] = hi;
}

// -------------------- weight transpose -> bf16 [N][K] --------------------
__global__ void __launch_bounds__(256) transpose_kernel(const float* __restrict__ src,
                                                        __nv_bfloat16* __restrict__ dst){
    __shared__ float t[32][33];
    const int tx = threadIdx.x, ty = threadIdx.y;
    int x = blockIdx.x*32 + tx;
    int y = blockIdx.y*32 + ty;
#pragma unroll
    for (int j=0;j<32;j+=8) t[ty+j][tx] = src[(long)(y+j)*1024 + x];
    __syncthreads();
    x = blockIdx.y*32 + tx;
    y = blockIdx.x*32 + ty;
#pragma unroll
    for (int j=0;j<32;j+=8)
        dst[(long)(y+j)*1024 + x] = __float2bfloat16_rn(t[tx][ty+j]);
}

// -------------------- LayerNorm (+pad), bf16 output --------------------
__global__ void __launch_bounds__(256) ln_kernel(
    const float* __restrict__ h, const float* __restrict__ gamma,
    const float* __restrict__ beta, __nv_bfloat16* __restrict__ X)
{
    const int row = blockIdx.x;
    const int b = row >> 11, r = row & 2047;
    const int tid = threadIdx.x;
    __nv_bfloat16* xo = X + (long)row * PD;
    if (r >= VALID_ROWS){
        __nv_bfloat162 z = __float22bfloat162_rn(make_float2(0.f,0.f));
        *(__nv_bfloat162*)&xo[tid*4]   = z;
        *(__nv_bfloat162*)&xo[tid*4+2] = z;
        return;
    }
    const float* hp = h + ((long)b*PS + r + (PCHUNK-1)) * PD;
    float4 v = *(const float4*)&hp[tid*4];
    float s  = v.x + v.y + v.z + v.w;
    float sq = v.x*v.x + v.y*v.y + v.z*v.z + v.w*v.w;
#pragma unroll
    for (int o=16;o;o>>=1){
        s  += __shfl_down_sync(0xffffffffu, s,  o);
        sq += __shfl_down_sync(0xffffffffu, sq, o);
    }
    __shared__ float rs_[8], rq_[8];
    __shared__ float mu_s, rstd_s;
    const int wid = tid>>5, lane = tid&31;
    if (!lane){ rs_[wid]=s; rq_[wid]=sq; }
    __syncthreads();
    if (tid==0){
        float ts=0.f, tq=0.f;
#pragma unroll
        for (int i=0;i<8;i++){ ts+=rs_[i]; tq+=rq_[i]; }
        float mu = ts * (1.0f/PD);
        float var = tq * (1.0f/PD) - mu*mu;
        mu_s = mu; rstd_s = rsqrtf(var + 1e-5f);
    }
    __syncthreads();
    const float mu = mu_s, rstd = rstd_s;
    float4 g  = *(const float4*)&gamma[tid*4];
    float4 be = *(const float4*)&beta[tid*4];
    float2 p0 = make_float2((v.x-mu)*rstd*g.x + be.x, (v.y-mu)*rstd*g.y + be.y);
    float2 p1 = make_float2((v.z-mu)*rstd*g.z + be.z, (v.w-mu)*rstd*g.w + be.w);
    *(__nv_bfloat162*)&xo[tid*4]   = __float22bfloat162_rn(p0);
    *(__nv_bfloat162*)&xo[tid*4+2] = __float22bfloat162_rn(p1);
}

// -------------------- attention (per b,c,h) --------------------
#define ATT_SMEM ((64*72*2 + 64*260) * 4)

__global__ void __launch_bounds__(128) attn_kernel(
    const float* __restrict__ Q, const float* __restrict__ Kb,
    const float* __restrict__ Vb, __nv_bfloat16* __restrict__ AO)
{
    extern __shared__ float sm[];
    float* Qs  = sm;
    float* KVs = sm + 64*72;
    float* Ss  = sm + 2*64*72;
    const int hh = blockIdx.x, c = blockIdx.y, b = blockIdx.z;
    const int tid = threadIdx.x, w = tid>>5, lane = tid&31;
    const int quad = lane>>2, qt = lane&3;
    const long qbase  = ((long)((b*PC + c)*PCHUNK))*PD + hh*PDK;
    const long kvbase = ((long)((b*PC + c)*PNL ))*PD + hh*PDK;

#pragma unroll
    for (int it=0; it<8; it++){
        int idx = tid + it*128;
        int r = idx>>4, c4 = idx&15;
        *(float4*)&Qs[r*72 + c4*4] = *(const float4*)&Q[qbase + (long)r*1024 + c4*4];
    }

    for (int jt=0; jt<4; jt++){
        __syncthreads();
#pragma unroll
        for (int it=0; it<8; it++){
            int idx = tid + it*128;
            int r = idx>>4, c4 = idx&15;
            *(float4*)&KVs[r*72 + c4*4] =
                *(const float4*)&Kb[kvbase + (long)(jt*64 + r)*1024 + c4*4];
        }
        __syncthreads();
        float acc[8][4] = {};
#pragma unroll
        for (int kk=0; kk<64; kk+=8){
            uint32_t af[4];
            const int ib = w*16;
            af[0]=f2tf32(Qs[(ib+quad  )*72 + kk+qt  ]);
            af[1]=f2tf32(Qs[(ib+quad+8)*72 + kk+qt  ]);
            af[2]=f2tf32(Qs[(ib+quad  )*72 + kk+qt+4]);
            af[3]=f2tf32(Qs[(ib+quad+8)*72 + kk+qt+4]);
#pragma unroll
            for (int ni=0; ni<8; ni++){
                uint32_t b0=f2tf32(KVs[(ni*8+quad)*72 + kk+qt  ]);
                uint32_t b1=f2tf32(KVs[(ni*8+quad)*72 + kk+qt+4]);
                mma_tf32(acc[ni], af[0],af[1],af[2],af[3], b0,b1);
            }
        }
#pragma unroll
        for (int ni=0; ni<8; ni++){
            const int i0 = w*16 + quad;
            const int j0 = jt*64 + ni*8 + qt*2;
            Ss[i0*260 + j0]       = acc[ni][0]*PSCALE;
            Ss[i0*260 + j0+1]     = acc[ni][1]*PSCALE;
            Ss[(i0+8)*260 + j0]   = acc[ni][2]*PSCALE;
            Ss[(i0+8)*260 + j0+1] = acc[ni][3]*PSCALE;
        }
    }
    __syncthreads();

    if (tid < 64){
        float* row = &Ss[tid*260];
        float m = -1e30f;
        for (int j=0;j<256;j++) m = fmaxf(m, row[j]);
        float ssum = 0.f;
        for (int j=0;j<256;j++){ float ev = __expf(row[j]-m); row[j]=ev; ssum+=ev; }
        const float inv = 1.0f/ssum;
        for (int j=0;j<256;j++) row[j]*=inv;
    }

    float accO[8][4] = {};
    for (int jt=0; jt<4; jt++){
        __syncthreads();
#pragma unroll
        for (int it=0; it<8; it++){
            int idx = tid + it*128;
            int r = idx>>4, c4 = idx&15;
            *(float4*)&KVs[r*72 + c4*4] =
                *(const float4*)&Vb[kvbase + (long)(jt*64 + r)*1024 + c4*4];
        }
        __syncthreads();
#pragma unroll
        for (int kk=0; kk<64; kk+=8){
            uint32_t af[4];
            const int ib = w*16;
            const int jcol = jt*64 + kk;
            af[0]=f2tf32(Ss[(ib+quad  )*260 + jcol+qt  ]);
            af[1]=f2tf32(Ss[(ib+quad+8)*260 + jcol+qt  ]);
            af[2]=f2tf32(Ss[(ib+quad  )*260 + jcol+qt+4]);
            af[3]=f2tf32(Ss[(ib+quad+8)*260 + jcol+qt+4]);
#pragma unroll
            for (int ni=0; ni<8; ni++){
                uint32_t b0=f2tf32(KVs[(kk+qt  )*72 + ni*8+quad]);
                uint32_t b1=f2tf32(KVs[(kk+qt+4)*72 + ni*8+quad]);
                mma_tf32(accO[ni], af[0],af[1],af[2],af[3], b0,b1);
            }
        }
    }
    // store bf16 (feeds O-GEMM)
#pragma unroll
    for (int ni=0; ni<8; ni++){
        const int i0 = w*16 + quad;
        const int d0 = ni*8 + qt*2;
        *(__nv_bfloat162*)&AO[qbase + (long)i0*1024 + d0] =
            __float22bfloat162_rn(make_float2(accO[ni][0], accO[ni][1]));
        *(__nv_bfloat162*)&AO[qbase + (long)(i0+8)*1024 + d0] =
            __float22bfloat162_rn(make_float2(accO[ni][2], accO[ni][3]));
    }
}

// -------------------- copy first 63 rows --------------------
__global__ void copy_head_kernel(const float* __restrict__ h, float* __restrict__ out){
    const int idx = blockIdx.x*256 + threadIdx.x;
    if (idx >= PB*(PCHUNK-1)*(PD/4)) return;
    const int b = idx / ((PCHUNK-1)*(PD/4));
    const int rem = idx % ((PCHUNK-1)*(PD/4));
    const int s = rem >> 8, c4 = rem & 255;
    const long o = ((long)b*PS + s)*PD + c4*4;
    *(float4*)&out[o] = *(const float4*)&h[o];
}

// -------------------- launch --------------------
extern "C" void kernel_launch(void* const* d_in, const int* in_sizes, int n_in,
                              void* d_out, int out_size)
{
    const float* h     = (const float*)d_in[0];
    const float* e     = (const float*)d_in[1];
    const float* Wq    = (const float*)d_in[2];
    const float* bq    = (const float*)d_in[3];
    const float* Wk    = (const float*)d_in[4];
    const float* bk    = (const float*)d_in[5];
    const float* Wv    = (const float*)d_in[6];
    const float* bv    = (const float*)d_in[7];
    const float* Wo    = (const float*)d_in[8];
    const float* bo    = (const float*)d_in[9];
    const float* gamma = (const float*)d_in[10];
    const float* beta  = (const float*)d_in[11];
    float* out = (float*)d_out;

    void *pX,*pE,*pQ,*pK,*pV,*pA,*pW;
    cudaGetSymbolAddress(&pX, g_X);
    cudaGetSymbolAddress(&pE, g_E);
    cudaGetSymbolAddress(&pQ, g_Q);
    cudaGetSymbolAddress(&pK, g_K);
    cudaGetSymbolAddress(&pV, g_V);
    cudaGetSymbolAddress(&pA, g_AO);
    cudaGetSymbolAddress(&pW, g_Wt);
    __nv_bfloat16* Wt = (__nv_bfloat16*)pW;

    cudaFuncSetAttribute(gemm_bf16_kernel<0>, cudaFuncAttributeMaxDynamicSharedMemorySize, G_SMEM);
    cudaFuncSetAttribute(gemm_bf16_kernel<1>, cudaFuncAttributeMaxDynamicSharedMemorySize, G_SMEM);
    cudaFuncSetAttribute(attn_kernel,         cudaFuncAttributeMaxDynamicSharedMemorySize, ATT_SMEM);

    // 0) operand prep
    transpose_kernel<<<dim3(32,32), dim3(32,8)>>>(Wq, Wt + 0*PD*PD);
    transpose_kernel<<<dim3(32,32), dim3(32,8)>>>(Wk, Wt + 1*PD*PD);
    transpose_kernel<<<dim3(32,32), dim3(32,8)>>>(Wv, Wt + 2*PD*PD);
    transpose_kernel<<<dim3(32,32), dim3(32,8)>>>(Wo, Wt + 3*PD*PD);
    convert_e_kernel<<<PB*PC*PNL*PD/1024, 256>>>(e, (__nv_bfloat16*)pE);
    ln_kernel<<<PB*PS, 256>>>(h, gamma, beta, (__nv_bfloat16*)pX);
    // 1) projections (bf16 tensor cores, fp32 accum)
    gemm_bf16_kernel<0><<<dim3(8,64),  256, G_SMEM>>>((const __nv_bfloat16*)pX, Wt + 0*PD*PD, bq, (float*)pQ, nullptr);
    gemm_bf16_kernel<0><<<dim3(8,256), 256, G_SMEM>>>((const __nv_bfloat16*)pE, Wt + 1*PD*PD, bk, (float*)pK, nullptr);
    gemm_bf16_kernel<0><<<dim3(8,256), 256, G_SMEM>>>((const __nv_bfloat16*)pE, Wt + 2*PD*PD, bv, (float*)pV, nullptr);
    // 2) attention
    attn_kernel<<<dim3(PH, PC, PB), 128, ATT_SMEM>>>((const float*)pQ, (const float*)pK,
                                                     (const float*)pV, (__nv_bfloat16*)pA);
    // 3) output projection + shifted residual
    gemm_bf16_kernel<1><<<dim3(8,64),  256, G_SMEM>>>((const __nv_bfloat16*)pA, Wt + 3*PD*PD, bo, out, h);
    // 4) head rows
    copy_head_kernel<<<(PB*(PCHUNK-1)*(PD/4) + 255)/256, 256>>>(h, out);
}